// round 7
// baseline (speedup 1.0000x reference)
#include <cuda_runtime.h>
#include <cuda_bf16.h>
#include <cuda_fp16.h>
#include <cstdint>

#define N_NODES 50000
#define N_EDGES 800000
#define IN_F    512
#define OUT_F   96
#define HPAD    128     // fp16 row stride (elements) -> 256B, line-aligned
#define ALPHA   0.1f
#define ITERS   10

// ---------------- device scratch ----------------
__device__ float  g_support[N_NODES * OUT_F];       // fp32 residual source
__device__ __half g_h0[N_NODES * HPAD];             // fp16 ping (padded rows)
__device__ __half g_h1[N_NODES * HPAD];             // fp16 pong
__device__ int    g_counts[N_NODES];
__device__ int    g_rowptr[N_NODES + 1];
__device__ int    g_offsets[N_NODES];
__device__ int2   g_edge[N_EDGES];                  // (col, half2(v,v) bits)
__device__ int    g_bsum[64];

__device__ __forceinline__ uint32_t smem_u32(const void* p) {
    uint32_t a;
    asm("{ .reg .u64 t; cvta.to.shared.u64 t, %1; cvt.u32.u64 %0, t; }" : "=r"(a) : "l"(p));
    return a;
}

// ---------------- CSR build ----------------
__global__ void zero_counts_kernel() {
    int i = blockIdx.x * blockDim.x + threadIdx.x;
    if (i < N_NODES) g_counts[i] = 0;
}
__global__ void hist_kernel(const int* __restrict__ dst) {
    int e = blockIdx.x * blockDim.x + threadIdx.x;
    if (e < N_EDGES) atomicAdd(&g_counts[dst[e]], 1);
}

#define SCAN_B 1024
#define N_SCAN_BLOCKS ((N_NODES + SCAN_B - 1) / SCAN_B)   // 49

__global__ void scan_block_kernel() {
    __shared__ int sh[SCAN_B];
    int tid = threadIdx.x;
    int i = blockIdx.x * SCAN_B + tid;
    int v = (i < N_NODES) ? g_counts[i] : 0;
    sh[tid] = v;
    __syncthreads();
    #pragma unroll
    for (int off = 1; off < SCAN_B; off <<= 1) {
        int t = (tid >= off) ? sh[tid - off] : 0;
        __syncthreads();
        sh[tid] += t;
        __syncthreads();
    }
    if (i < N_NODES) g_rowptr[i] = sh[tid] - v;     // block-local exclusive
    if (tid == SCAN_B - 1) g_bsum[blockIdx.x] = sh[tid];
}

__global__ void scan_add_kernel() {
    __shared__ int pre[N_SCAN_BLOCKS + 1];
    int tid = threadIdx.x;
    if (tid == 0) {
        int acc = 0;
        #pragma unroll 1
        for (int b = 0; b < N_SCAN_BLOCKS; b++) { pre[b] = acc; acc += g_bsum[b]; }
        pre[N_SCAN_BLOCKS] = acc;
    }
    __syncthreads();
    int i = blockIdx.x * SCAN_B + tid;
    if (i < N_NODES) {
        int v = g_rowptr[i] + pre[blockIdx.x];
        g_rowptr[i] = v;
        g_offsets[i] = v;
    }
    if (blockIdx.x == 0 && tid == 0) g_rowptr[N_NODES] = pre[N_SCAN_BLOCKS];
}

__global__ void scatter_kernel(const int* __restrict__ src,
                               const int* __restrict__ dst,
                               const float* __restrict__ val) {
    int e = blockIdx.x * blockDim.x + threadIdx.x;
    if (e < N_EDGES) {
        int d = dst[e];
        int pos = atomicAdd(&g_offsets[d], 1);
        float v = val[e] * (1.0f - ALPHA);
        __half2 hv = __floats2half2_rn(v, v);
        g_edge[pos] = make_int2(src[e], *reinterpret_cast<int*>(&hv));
    }
}

// ---------------- HMMA GEMM: g_support = x @ W ----------------
// 3-term bf16 split: D = xh@Wh + xh@Wl + xl@Wh  (fp32 accumulate)
#define BM 128
#define BK 32
#define APAD 40

__device__ __forceinline__ void ldmat4(uint32_t* r, uint32_t addr) {
    asm volatile("ldmatrix.sync.aligned.m8n8.x4.shared.b16 {%0,%1,%2,%3}, [%4];"
                 : "=r"(r[0]), "=r"(r[1]), "=r"(r[2]), "=r"(r[3]) : "r"(addr));
}
__device__ __forceinline__ void mma16816(float* c, const uint32_t* a,
                                         uint32_t b0, uint32_t b1) {
    asm volatile("mma.sync.aligned.m16n8k16.row.col.f32.bf16.bf16.f32 "
                 "{%0,%1,%2,%3}, {%4,%5,%6,%7}, {%8,%9}, {%0,%1,%2,%3};"
                 : "+f"(c[0]), "+f"(c[1]), "+f"(c[2]), "+f"(c[3])
                 : "r"(a[0]), "r"(a[1]), "r"(a[2]), "r"(a[3]), "r"(b0), "r"(b1));
}

__global__ __launch_bounds__(256) void gemm_mma_kernel(const float* __restrict__ x,
                                                       const float* __restrict__ w) {
    __shared__ __nv_bfloat16 Ahi[BM * APAD];
    __shared__ __nv_bfloat16 Alo[BM * APAD];
    __shared__ __nv_bfloat16 Bhi[OUT_F * APAD];   // n-major: Bhi[n*APAD + k]
    __shared__ __nv_bfloat16 Blo[OUT_F * APAD];

    int tid = threadIdx.x;
    int wid = tid >> 5;
    int lane = tid & 31;
    int row0 = blockIdx.x * BM;

    float acc[12][4];
    #pragma unroll
    for (int j = 0; j < 12; j++)
        #pragma unroll
        for (int q = 0; q < 4; q++) acc[j][q] = 0.0f;

    uint32_t ahi_base = smem_u32(Ahi);
    uint32_t alo_base = smem_u32(Alo);

    int lm_row = wid * 16 + (lane & 7) + ((lane >> 3) & 1) * 8;
    int lm_k8  = (lane >> 4) * 8;
    int bn = lane >> 2;
    int bk = (lane & 3) * 2;

    for (int c = 0; c < IN_F / BK; c++) {
        int k0g = c * BK;

        {   // A tile: 128 rows x 32 k, split hi/lo
            int r = tid >> 1;
            int kh = (tid & 1) * 16;
            int gr = row0 + r;
            const float4* src = reinterpret_cast<const float4*>(
                &x[(long)gr * IN_F + k0g + kh]);
            #pragma unroll
            for (int q = 0; q < 4; q++) {
                float4 v = (gr < N_NODES) ? src[q]
                                          : make_float4(0.f, 0.f, 0.f, 0.f);
                float vv[4] = {v.x, v.y, v.z, v.w};
                __nv_bfloat162 th2[2], tl2[2];
                #pragma unroll
                for (int p = 0; p < 4; p++) {
                    __nv_bfloat16 h = __float2bfloat16(vv[p]);
                    __nv_bfloat16 l = __float2bfloat16(vv[p] - __bfloat162float(h));
                    if (p & 1) { th2[p >> 1].y = h; tl2[p >> 1].y = l; }
                    else       { th2[p >> 1].x = h; tl2[p >> 1].x = l; }
                }
                int o = r * APAD + kh + q * 4;
                *reinterpret_cast<__nv_bfloat162*>(&Ahi[o])     = th2[0];
                *reinterpret_cast<__nv_bfloat162*>(&Ahi[o + 2]) = th2[1];
                *reinterpret_cast<__nv_bfloat162*>(&Alo[o])     = tl2[0];
                *reinterpret_cast<__nv_bfloat162*>(&Alo[o + 2]) = tl2[1];
            }
        }

        #pragma unroll
        for (int j = 0; j < 12; j++) {   // W tile: 32 k x 96 n -> [n][k]
            int idx = j * 256 + tid;
            int k = idx / OUT_F;
            int n = idx - k * OUT_F;
            float v = w[(long)(k0g + k) * OUT_F + n];
            __nv_bfloat16 h = __float2bfloat16(v);
            __nv_bfloat16 l = __float2bfloat16(v - __bfloat162float(h));
            Bhi[n * APAD + k] = h;
            Blo[n * APAD + k] = l;
        }
        __syncthreads();

        #pragma unroll
        for (int ks = 0; ks < 2; ks++) {
            uint32_t a_off = (uint32_t)(lm_row * APAD + ks * 16 + lm_k8) * 2;
            uint32_t ah[4], al[4];
            ldmat4(ah, ahi_base + a_off);
            ldmat4(al, alo_base + a_off);
            int kk = ks * 16 + bk;
            #pragma unroll
            for (int j = 0; j < 12; j++) {
                int n = j * 8 + bn;
                uint32_t bh0 = *reinterpret_cast<const uint32_t*>(&Bhi[n * APAD + kk]);
                uint32_t bh1 = *reinterpret_cast<const uint32_t*>(&Bhi[n * APAD + kk + 8]);
                uint32_t bl0 = *reinterpret_cast<const uint32_t*>(&Blo[n * APAD + kk]);
                uint32_t bl1 = *reinterpret_cast<const uint32_t*>(&Blo[n * APAD + kk + 8]);
                mma16816(acc[j], ah, bh0, bh1);
                mma16816(acc[j], ah, bl0, bl1);
                mma16816(acc[j], al, bh0, bh1);
            }
        }
        __syncthreads();
    }

    int r0 = row0 + wid * 16 + (lane >> 2);
    int cb = (lane & 3) * 2;
    #pragma unroll
    for (int j = 0; j < 12; j++) {
        int cc = j * 8 + cb;
        if (r0 < N_NODES) {
            float2 t = make_float2(acc[j][0], acc[j][1]);
            *reinterpret_cast<float2*>(&g_support[(long)r0 * OUT_F + cc]) = t;
        }
        if (r0 + 8 < N_NODES) {
            float2 t = make_float2(acc[j][2], acc[j][3]);
            *reinterpret_cast<float2*>(&g_support[(long)(r0 + 8) * OUT_F + cc]) = t;
        }
    }
}

// ---------------- SPMM + residual + relu ----------------
// fp16 iters: gather padded half2 rows, accumulate with HFMA2 (no F2F in
// the hot loop), flush to fp32 every 8 edges.
// Lane owns features {2l, 2l+1}; lanes 0-15 also own {64+2l, 64+2l+1}.
// in_sel: 0 = g_support (fp32), 1 = g_h0, 2 = g_h1
// out_sel: 1 = g_h0, 2 = g_h1, 3 = d_out (fp32)
__global__ __launch_bounds__(256) void spmm_kernel(float* __restrict__ dout,
                                                   int in_sel, int out_sel) {
    int row = (blockIdx.x * blockDim.x + threadIdx.x) >> 5;
    int lane = threadIdx.x & 31;
    if (row >= N_NODES) return;

    int beg = g_rowptr[row];
    int end = g_rowptr[row + 1];
    bool lo = lane < 16;

    float f00 = 0.f, f01 = 0.f, f10 = 0.f, f11 = 0.f;

    if (in_sel == 0) {
        // iteration 1: fp32 support input
        const float2* __restrict__ h = reinterpret_cast<const float2*>(g_support);
        for (int e = beg; e < end; e++) {
            int2 ed = __ldg(&g_edge[e]);
            __half2 hv = *reinterpret_cast<__half2*>(&ed.y);
            float v = __low2float(hv);
            const float2* p = h + (long)ed.x * 48;
            float2 u0 = __ldg(p + lane);
            f00 = fmaf(v, u0.x, f00);
            f01 = fmaf(v, u0.y, f01);
            if (lo) {
                float2 u1 = __ldg(p + 32 + lane);
                f10 = fmaf(v, u1.x, f10);
                f11 = fmaf(v, u1.y, f11);
            }
        }
    } else {
        const __half2* __restrict__ h = reinterpret_cast<const __half2*>(
            (in_sel == 1) ? g_h0 : g_h1);
        int e = beg;
        while (e < end) {
            int ce = min(end, e + 8);
            __half2 c0 = __floats2half2_rn(0.f, 0.f);
            __half2 c1 = c0;
            #pragma unroll 2
            for (; e < ce; e++) {
                int2 ed = __ldg(&g_edge[e]);
                __half2 vh = *reinterpret_cast<__half2*>(&ed.y);
                const __half2* p = h + (long)ed.x * (HPAD / 2);
                __half2 u0 = __ldg(p + lane);
                c0 = __hfma2(vh, u0, c0);
                if (lo) {
                    __half2 u1 = __ldg(p + 32 + lane);
                    c1 = __hfma2(vh, u1, c1);
                }
            }
            f00 += __low2float(c0);
            f01 += __high2float(c0);
            f10 += __low2float(c1);
            f11 += __high2float(c1);
        }
    }

    // residual + relu
    long ob = (long)row * OUT_F;
    float2 s0 = *reinterpret_cast<const float2*>(&g_support[ob + 2 * lane]);
    float r00 = fmaxf(fmaf(ALPHA, s0.x, f00), 0.0f);
    float r01 = fmaxf(fmaf(ALPHA, s0.y, f01), 0.0f);
    float r10 = 0.f, r11 = 0.f;
    if (lo) {
        float2 s1 = *reinterpret_cast<const float2*>(&g_support[ob + 64 + 2 * lane]);
        r10 = fmaxf(fmaf(ALPHA, s1.x, f10), 0.0f);
        r11 = fmaxf(fmaf(ALPHA, s1.y, f11), 0.0f);
    }

    if (out_sel == 3) {
        *reinterpret_cast<float2*>(&dout[ob + 2 * lane]) = make_float2(r00, r01);
        if (lo)
            *reinterpret_cast<float2*>(&dout[ob + 64 + 2 * lane]) = make_float2(r10, r11);
    } else {
        __half2* out = reinterpret_cast<__half2*>(
            ((out_sel == 1) ? g_h0 : g_h1) + (long)row * HPAD);
        out[lane] = __floats2half2_rn(r00, r01);
        if (lo) out[32 + lane] = __floats2half2_rn(r10, r11);
    }
}

// ---------------- launch ----------------
extern "C" void kernel_launch(void* const* d_in, const int* in_sizes, int n_in,
                              void* d_out, int out_size) {
    const float* x  = (const float*)d_in[0];
    const float* w  = (const float*)d_in[1];
    const int* esrc = (const int*)d_in[2];
    const int* edst = (const int*)d_in[3];
    const float* ev = (const float*)d_in[4];
    float* dout = (float*)d_out;

    // CSR build
    zero_counts_kernel<<<(N_NODES + 255) / 256, 256>>>();
    hist_kernel<<<(N_EDGES + 255) / 256, 256>>>(edst);
    scan_block_kernel<<<N_SCAN_BLOCKS, SCAN_B>>>();
    scan_add_kernel<<<N_SCAN_BLOCKS, SCAN_B>>>();
    scatter_kernel<<<(N_EDGES + 255) / 256, 256>>>(esrc, edst, ev);

    // support = x @ W  (HMMA, 3-term bf16 split)
    gemm_mma_kernel<<<(N_NODES + BM - 1) / BM, 256>>>(x, w);

    // 10 propagation iterations:
    //   it1: support(fp32) -> h0 ; it2..9 ping-pong ; it10 -> d_out(fp32)
    int spmm_blocks = (N_NODES * 32 + 255) / 256;
    for (int it = 1; it <= ITERS; it++) {
        int in_sel  = (it == 1) ? 0 : ((it & 1) == 0 ? 1 : 2);
        int out_sel = (it == ITERS) ? 3 : (((it + 1) & 1) == 0 ? 2 : 1);
        spmm_kernel<<<spmm_blocks, 256>>>(dout, in_sel, out_sel);
    }
}